// round 5
// baseline (speedup 1.0000x reference)
#include <cuda_runtime.h>
#include <cstdint>

// Max edge count for the static scratch table (problem uses E = 2,000,000).
#define MAX_E 2000000

// Padded unit-direction table: float4 so each gather is one aligned 16B load
// (single 32B L2 sector). 2M * 16B = 32 MB, fits comfortably in L2 (~126 MB).
__device__ float4 g_dir[MAX_E];

// ---------------------------------------------------------------------------
// Kernel 1: dir[i] = vec[i] / max(dist[i], 1e-5)
// ---------------------------------------------------------------------------
__global__ void __launch_bounds__(256)
dir_kernel(const float* __restrict__ dist,
           const float* __restrict__ vec,
           int E)
{
    int i = blockIdx.x * blockDim.x + threadIdx.x;
    if (i >= E) return;
    float d   = fmaxf(dist[i], 1e-5f);
    float inv = __fdividef(1.0f, d);
    float x = vec[3 * i + 0];
    float y = vec[3 * i + 1];
    float z = vec[3 * i + 2];
    g_dir[i] = make_float4(x * inv, y * inv, z * inv, 0.0f);
}

// ---------------------------------------------------------------------------
// Kernel 2: out[a] = acos(0.95 * dot(dir[src[a]], dir[dst[a]]))
// Four pairs per thread: 128-bit int32-index loads, 128-bit output stores.
// ---------------------------------------------------------------------------
__global__ void __launch_bounds__(256)
angle_kernel4(const int* __restrict__ src,
              const int* __restrict__ dst,
              float* __restrict__ out,
              int n_vec4)   // number of 4-pair groups (A/4)
{
    int i = blockIdx.x * blockDim.x + threadIdx.x;
    if (i >= n_vec4) return;

    int4 s4 = reinterpret_cast<const int4*>(src)[i];
    int4 d4 = reinterpret_cast<const int4*>(dst)[i];

    float4 a0 = g_dir[s4.x];
    float4 b0 = g_dir[d4.x];
    float4 a1 = g_dir[s4.y];
    float4 b1 = g_dir[d4.y];
    float4 a2 = g_dir[s4.z];
    float4 b2 = g_dir[d4.z];
    float4 a3 = g_dir[s4.w];
    float4 b3 = g_dir[d4.w];

    float c0 = fmaf(a0.x, b0.x, fmaf(a0.y, b0.y, a0.z * b0.z));
    float c1 = fmaf(a1.x, b1.x, fmaf(a1.y, b1.y, a1.z * b1.z));
    float c2 = fmaf(a2.x, b2.x, fmaf(a2.y, b2.y, a2.z * b2.z));
    float c3 = fmaf(a3.x, b3.x, fmaf(a3.y, b3.y, a3.z * b3.z));

    float4 r;
    r.x = acosf(0.95f * c0);
    r.y = acosf(0.95f * c1);
    r.z = acosf(0.95f * c2);
    r.w = acosf(0.95f * c3);
    reinterpret_cast<float4*>(out)[i] = r;
}

// Scalar tail for A not divisible by 4 (defensive; A = 20M is divisible).
__global__ void angle_kernel_tail(const int* __restrict__ src,
                                  const int* __restrict__ dst,
                                  float* __restrict__ out,
                                  int start, int A)
{
    int i = start + blockIdx.x * blockDim.x + threadIdx.x;
    if (i >= A) return;
    float4 a = g_dir[src[i]];
    float4 b = g_dir[dst[i]];
    float c = fmaf(a.x, b.x, fmaf(a.y, b.y, a.z * b.z));
    out[i] = acosf(0.95f * c);
}

// ---------------------------------------------------------------------------
// Inputs (metadata order): distances[E] f32, vec[E*3] f32,
//                          angle_src[A] i32, angle_dst[A] i32
// Output: angles[A] f32
// ---------------------------------------------------------------------------
extern "C" void kernel_launch(void* const* d_in, const int* in_sizes, int n_in,
                              void* d_out, int out_size)
{
    const float* dist = (const float*)d_in[0];
    const float* vec  = (const float*)d_in[1];
    const int*   src  = (const int*)d_in[2];
    const int*   dst  = (const int*)d_in[3];
    float*       out  = (float*)d_out;

    int E = in_sizes[0];
    if (E > MAX_E) E = MAX_E;
    int A = in_sizes[2];

    const int TPB = 256;
    dir_kernel<<<(E + TPB - 1) / TPB, TPB>>>(dist, vec, E);

    int n4 = A / 4;
    if (n4 > 0)
        angle_kernel4<<<(n4 + TPB - 1) / TPB, TPB>>>(src, dst, out, n4);

    int tail_start = n4 * 4;
    if (A > tail_start)
        angle_kernel_tail<<<(A - tail_start + TPB - 1) / TPB, TPB>>>(
            src, dst, out, tail_start, A);
}